// round 8
// baseline (speedup 1.0000x reference)
#include <cuda_runtime.h>
#include <math.h>

#define BATCH   64
#define MOL     50
#define PRO     500
#define HID     32
#define HEADS   8
#define N_MOL   (BATCH*MOL)      // 3200
#define N_PRO   (BATCH*PRO)      // 32000
#define N_ATOM  (N_MOL + N_PRO)  // 35200
#define PAIRS   (N_MOL*PRO)      // 1,600,000

#define MPB     5                  // mol rows per tile
#define PSPLIT  250                // pro atoms per tile
#define TPB     256
#define GPB     (MOL / MPB)        // 10 mol groups per batch
#define PAIR_BLOCKS (BATCH * GPB * (PRO / PSPLIT))   // 1280

// Per-atom layout (8 float4 = 32 floats):
//   [0,1]=sig raw halves, [2,3]=mu raw halves, [4,5]=exp(sig), [6,7]=exp(mu)
__device__ float g_mol_half[N_MOL * 32];
__device__ float g_pro_half[N_PRO * 32];
__device__ float g_acc[BATCH * HEADS];     // per-batch mu sums
__device__ unsigned int g_done;            // pair-block completion counter

__device__ __forceinline__ float elu1(float x) {
    return x > 0.0f ? x : (__expf(x) - 1.0f);
}

// Packed f32x2 helpers (ptxas will not auto-pack; must come from PTX)
__device__ __forceinline__ unsigned long long addx2(unsigned long long a, unsigned long long b) {
    unsigned long long r;
    asm("add.rn.f32x2 %0, %1, %2;" : "=l"(r) : "l"(a), "l"(b));
    return r;
}
__device__ __forceinline__ unsigned long long mulx2(unsigned long long a, unsigned long long b) {
    unsigned long long r;
    asm("mul.rn.f32x2 %0, %1, %2;" : "=l"(r) : "l"(a), "l"(b));
    return r;
}
union F4u { float4 f; ulonglong2 u; };

// ---------------------------------------------------------------------------
// Kernel 1: per-atom half projections + exp of halves, split-k.
// 2 threads per (atom, {sigma|mu}); shfl_xor(1) combines k-halves.
// ---------------------------------------------------------------------------
__global__ void __launch_bounds__(TPB) precompute_kernel(
        const float* __restrict__ mol_feats,
        const float* __restrict__ pro_feats,
        const float* __restrict__ spatial,
        const float* __restrict__ W_sigma,
        const float* __restrict__ b_sigma,
        const float* __restrict__ W_mu,
        const float* __restrict__ b_mu) {
    __shared__ float4 s_W[256];   // [0,128)=W_sigma, [128,256)=W_mu
    for (int i = threadIdx.x; i < 256; i += TPB) {
        const float* src = (i < 128) ? W_sigma : W_mu;
        s_W[i] = ((const float4*)src)[i & 127];
    }
    __syncthreads();

    int t = blockIdx.x * TPB + threadIdx.x;
    if (t < BATCH * HEADS) g_acc[t] = 0.0f;
    if (t == 0) g_done = 0u;

    const int khalf = t & 1;
    const int pid   = t >> 1;                     // [0, 2*N_ATOM)
    const int which = (pid >= N_ATOM) ? 1 : 0;    // 0 = sigma, 1 = mu
    const int atom  = which ? (pid - N_ATOM) : pid;
    const float4* sW = s_W + which * 128;

    float4 x[4];
    float acc[HEADS];
    int wrow;
    float4* abase;   // atom's 8-float4 block

    if (atom < N_MOL) {
        const float4* f = (const float4*)(mol_feats + (size_t)atom * HID + khalf * 16);
        #pragma unroll
        for (int k = 0; k < 4; k++) x[k] = f[k];
        if (khalf == 0) {
            const float4* bsel = which ? (const float4*)b_mu : (const float4*)b_sigma;
            float4 b0 = bsel[0], b1 = bsel[1];
            acc[0] = b0.x; acc[1] = b0.y; acc[2] = b0.z; acc[3] = b0.w;
            acc[4] = b1.x; acc[5] = b1.y; acc[6] = b1.z; acc[7] = b1.w;
        } else {
            #pragma unroll
            for (int h = 0; h < HEADS; h++) acc[h] = 0.0f;
        }
        wrow = khalf * 16;
        abase = (float4*)(g_mol_half + (size_t)atom * 32);
    } else {
        int a = atom - N_MOL;
        const float4* f = (const float4*)(pro_feats + (size_t)a * HID + khalf * 16);
        const float4* s = (const float4*)(spatial   + (size_t)a * HID + khalf * 16);
        #pragma unroll
        for (int k = 0; k < 4; k++) {
            float4 fv = f[k], sv = s[k];
            x[k].x = fv.x * sv.x; x[k].y = fv.y * sv.y;
            x[k].z = fv.z * sv.z; x[k].w = fv.w * sv.w;
        }
        #pragma unroll
        for (int h = 0; h < HEADS; h++) acc[h] = 0.0f;
        wrow = HID + khalf * 16;
        abase = (float4*)(g_pro_half + (size_t)a * 32);
    }

    #pragma unroll
    for (int k = 0; k < 16; k++) {
        float xv = ((const float*)x)[k];
        float4 w0 = sW[(wrow + k) * 2 + 0];
        float4 w1 = sW[(wrow + k) * 2 + 1];
        acc[0] = fmaf(xv, w0.x, acc[0]); acc[1] = fmaf(xv, w0.y, acc[1]);
        acc[2] = fmaf(xv, w0.z, acc[2]); acc[3] = fmaf(xv, w0.w, acc[3]);
        acc[4] = fmaf(xv, w1.x, acc[4]); acc[5] = fmaf(xv, w1.y, acc[5]);
        acc[6] = fmaf(xv, w1.z, acc[6]); acc[7] = fmaf(xv, w1.w, acc[7]);
    }

    #pragma unroll
    for (int h = 0; h < HEADS; h++)
        acc[h] += __shfl_xor_sync(0xffffffffu, acc[h], 1);

    // khalf=0 lane owns elements 0-3, khalf=1 owns 4-7 (full combined sums).
    float v0 = acc[khalf * 4 + 0], v1 = acc[khalf * 4 + 1];
    float v2 = acc[khalf * 4 + 2], v3 = acc[khalf * 4 + 3];
    int rs = which * 2 + khalf;
    abase[rs]     = make_float4(v0, v1, v2, v3);
    abase[4 + rs] = make_float4(__expf(v0), __expf(v1), __expf(v2), __expf(v3));
}

// ---------------------------------------------------------------------------
// Kernel 2: per-pair sigma/mu via branchless ELU:
//   elu(m+p)+c = fmax(m+p,0) + fmin(exp(m)*exp(p),1) + (c-1)
// No MUFU / predication in the hot loop; packed f32x2 add/mul.
// ---------------------------------------------------------------------------
__global__ void __launch_bounds__(TPB, 5) pair_kernel(
        float* __restrict__ mu_out, float* __restrict__ sigma_out,
        const float* __restrict__ W1, const float* __restrict__ b1,
        const float* __restrict__ W2, const float* __restrict__ b2,
        float* __restrict__ y_out) {
    __shared__ float4 s_sig [PSPLIT * 2];
    __shared__ float4 s_mu  [PSPLIT * 2];
    __shared__ float4 s_esig[PSPLIT * 2];
    __shared__ float4 s_emu [PSPLIT * 2];
    __shared__ float4 s_molsig[MPB * 2], s_molmu[MPB * 2];
    __shared__ float4 s_molesig[MPB * 2], s_molemu[MPB * 2];
    __shared__ float  s_red[(TPB / 32) * 8];
    __shared__ int    s_last;

    const int tile  = blockIdx.x;
    const int ph    = tile & 1;
    const int g     = tile >> 1;
    const int batch = g / GPB;
    const int mg    = g % GPB;
    const int mol0  = batch * MOL + mg * MPB;
    const int pro0  = ph * PSPLIT;

    // Stage pro tile: 250 atoms x 8 float4, de-interleaved.
    const float4* gp = (const float4*)g_pro_half + ((size_t)batch * PRO + pro0) * 8;
    for (int i = threadIdx.x; i < PSPLIT * 8; i += TPB) {
        int a = i >> 3, c = i & 7;
        float4 val = gp[i];
        int s = a * 2 + (c & 1);
        switch (c >> 1) {
            case 0: s_sig[s]  = val; break;
            case 1: s_mu[s]   = val; break;
            case 2: s_esig[s] = val; break;
            default: s_emu[s] = val; break;
        }
    }
    const float4* gm = (const float4*)g_mol_half + (size_t)mol0 * 8;
    if (threadIdx.x < MPB * 8) {
        int a = threadIdx.x >> 3, c = threadIdx.x & 7;
        float4 val = gm[threadIdx.x];
        int s = a * 2 + (c & 1);
        switch (c >> 1) {
            case 0: s_molsig[s]  = val; break;
            case 1: s_molmu[s]   = val; break;
            case 2: s_molesig[s] = val; break;
            default: s_molemu[s] = val; break;
        }
    }
    __syncthreads();

    union { float2 f; unsigned long long u; } c01;
    c01.f.x = 0.1f; c01.f.y = 0.1f;

    F4u acc; acc.f = make_float4(0.f, 0.f, 0.f, 0.f);
    const int h = threadIdx.x & 1;   // stride TPB is even -> parity fixed per thread

    #pragma unroll
    for (int lm = 0; lm < MPB; lm++) {
        const size_t base = ((size_t)(mol0 + lm) * PRO + pro0) * 2;
        float4* so = (float4*)sigma_out + base;
        float4* mo = (float4*)mu_out    + base;

        F4u ms, ems, mm, emm;
        ms.f  = s_molsig[lm * 2 + h];  ems.f = s_molesig[lm * 2 + h];
        mm.f  = s_molmu[lm * 2 + h];   emm.f = s_molemu[lm * 2 + h];

        for (int v = threadIdx.x; v < PSPLIT * 2; v += TPB) {
            // ---- sigma ----
            {
                F4u ps, eps; ps.f = s_sig[v]; eps.f = s_esig[v];
                F4u x, e, mx, mn, r;
                x.u.x = addx2(ms.u.x, ps.u.x);   x.u.y = addx2(ms.u.y, ps.u.y);
                e.u.x = mulx2(ems.u.x, eps.u.x); e.u.y = mulx2(ems.u.y, eps.u.y);
                mx.f.x = fmaxf(x.f.x, 0.f); mx.f.y = fmaxf(x.f.y, 0.f);
                mx.f.z = fmaxf(x.f.z, 0.f); mx.f.w = fmaxf(x.f.w, 0.f);
                mn.f.x = fminf(e.f.x, 1.f); mn.f.y = fminf(e.f.y, 1.f);
                mn.f.z = fminf(e.f.z, 1.f); mn.f.w = fminf(e.f.w, 1.f);
                r.u.x = addx2(mx.u.x, mn.u.x); r.u.y = addx2(mx.u.y, mn.u.y);
                r.u.x = addx2(r.u.x, c01.u);   r.u.y = addx2(r.u.y, c01.u);
                __stcs(so + v, r.f);
            }
            // ---- mu (c-1 = 0: no const add) ----
            {
                F4u pm, epm; pm.f = s_mu[v]; epm.f = s_emu[v];
                F4u x, e, mx, mn, r;
                x.u.x = addx2(mm.u.x, pm.u.x);   x.u.y = addx2(mm.u.y, pm.u.y);
                e.u.x = mulx2(emm.u.x, epm.u.x); e.u.y = mulx2(emm.u.y, epm.u.y);
                mx.f.x = fmaxf(x.f.x, 0.f); mx.f.y = fmaxf(x.f.y, 0.f);
                mx.f.z = fmaxf(x.f.z, 0.f); mx.f.w = fmaxf(x.f.w, 0.f);
                mn.f.x = fminf(e.f.x, 1.f); mn.f.y = fminf(e.f.y, 1.f);
                mn.f.z = fminf(e.f.z, 1.f); mn.f.w = fminf(e.f.w, 1.f);
                r.u.x = addx2(mx.u.x, mn.u.x); r.u.y = addx2(mx.u.y, mn.u.y);
                __stcs(mo + v, r.f);
                acc.u.x = addx2(acc.u.x, r.u.x);
                acc.u.y = addx2(acc.u.y, r.u.y);
            }
        }
    }

    // Reduce: same-parity lanes share head set; xor offsets >=2 preserve parity.
    #pragma unroll
    for (int off = 16; off >= 2; off >>= 1) {
        acc.f.x += __shfl_xor_sync(0xffffffffu, acc.f.x, off);
        acc.f.y += __shfl_xor_sync(0xffffffffu, acc.f.y, off);
        acc.f.z += __shfl_xor_sync(0xffffffffu, acc.f.z, off);
        acc.f.w += __shfl_xor_sync(0xffffffffu, acc.f.w, off);
    }
    int warp = threadIdx.x >> 5, lane = threadIdx.x & 31;
    if (lane < 2) {   // lane0: heads 0-3, lane1: heads 4-7
        s_red[warp * 8 + lane * 4 + 0] = acc.f.x;
        s_red[warp * 8 + lane * 4 + 1] = acc.f.y;
        s_red[warp * 8 + lane * 4 + 2] = acc.f.z;
        s_red[warp * 8 + lane * 4 + 3] = acc.f.w;
    }
    __syncthreads();
    if (threadIdx.x < 8) {
        float s = 0.f;
        #pragma unroll
        for (int w = 0; w < TPB / 32; w++) s += s_red[w * 8 + threadIdx.x];
        atomicAdd(&g_acc[batch * HEADS + threadIdx.x], s);
        __threadfence();
    }
    __syncthreads();

    if (threadIdx.x == 0) {
        unsigned int done = atomicAdd(&g_done, 1u);
        s_last = (done == PAIR_BLOCKS - 1) ? 1 : 0;
    }
    __syncthreads();
    if (s_last && threadIdx.x < BATCH) {
        int b = threadIdx.x;
        float v[HEADS];
        #pragma unroll
        for (int hh = 0; hh < HEADS; hh++)
            v[hh] = __ldcg(&g_acc[b * HEADS + hh]) * 0.001f;
        float y = __ldg(&b2[0]);
        #pragma unroll
        for (int jj = 0; jj < 2 * HEADS; jj++) {
            float hsum = __ldg(&b1[jj]);
            #pragma unroll
            for (int hh = 0; hh < HEADS; hh++)
                hsum = fmaf(v[hh], __ldg(&W1[hh * 2 * HEADS + jj]), hsum);
            y = fmaf(elu1(hsum), __ldg(&W2[jj]), y);
        }
        y_out[b] = y;
    }
}

extern "C" void kernel_launch(void* const* d_in, const int* in_sizes, int n_in,
                              void* d_out, int out_size) {
    const float* mol_feats = (const float*)d_in[0];
    const float* pro_feats = (const float*)d_in[1];
    const float* spatial   = (const float*)d_in[2];
    const float* W_sigma   = (const float*)d_in[3];
    const float* b_sigma   = (const float*)d_in[4];
    const float* W_mu      = (const float*)d_in[5];
    const float* b_mu      = (const float*)d_in[6];
    const float* W1        = (const float*)d_in[7];
    const float* b1        = (const float*)d_in[8];
    const float* W2        = (const float*)d_in[9];
    const float* b2        = (const float*)d_in[10];

    float* out       = (float*)d_out;
    float* mu_out    = out;
    float* sigma_out = out + (size_t)PAIRS * HEADS;
    float* y_out     = out + (size_t)2 * PAIRS * HEADS;

    int total_threads = 4 * N_ATOM;   // 140800 = 550 blocks exactly
    precompute_kernel<<<total_threads / TPB, TPB>>>(
        mol_feats, pro_feats, spatial, W_sigma, b_sigma, W_mu, b_mu);
    pair_kernel<<<PAIR_BLOCKS, TPB>>>(mu_out, sigma_out, W1, b1, W2, b2, y_out);
}

// round 9
// speedup vs baseline: 1.4012x; 1.4012x over previous
#include <cuda_runtime.h>
#include <math.h>

#define BATCH   64
#define MOL     50
#define PRO     500
#define HID     32
#define HEADS   8
#define N_MOL   (BATCH*MOL)      // 3200
#define N_PRO   (BATCH*PRO)      // 32000
#define N_ATOM  (N_MOL + N_PRO)  // 35200
#define PAIRS   (N_MOL*PRO)      // 1,600,000

#define MPB     5                  // mol rows per tile
#define PSPLIT  250                // pro atoms per tile
#define TPB     256
#define GPB     (MOL / MPB)        // 10 mol groups per batch
#define PAIR_BLOCKS (BATCH * GPB * (PRO / PSPLIT))   // 1280

// Per-atom layout (8 float4 = 32 floats):
//   [0,1]=sig raw halves, [2,3]=mu raw halves, [4,5]=exp(sig), [6,7]=exp(mu)
__device__ float g_mol_half[N_MOL * 32];
__device__ float g_pro_half[N_PRO * 32];
__device__ float g_acc[BATCH * HEADS];     // per-batch mu sums
__device__ unsigned int g_done;            // pair-block completion counter

__device__ __forceinline__ float elu1(float x) {
    return x > 0.0f ? x : (__expf(x) - 1.0f);
}

// ---------------------------------------------------------------------------
// Kernel 1: per-atom half projections + exp of halves, split-k.
// 2 threads per (atom, {sigma|mu}); shfl_xor(1) combines k-halves.
// ---------------------------------------------------------------------------
__global__ void __launch_bounds__(TPB) precompute_kernel(
        const float* __restrict__ mol_feats,
        const float* __restrict__ pro_feats,
        const float* __restrict__ spatial,
        const float* __restrict__ W_sigma,
        const float* __restrict__ b_sigma,
        const float* __restrict__ W_mu,
        const float* __restrict__ b_mu) {
    __shared__ float4 s_W[256];   // [0,128)=W_sigma, [128,256)=W_mu
    for (int i = threadIdx.x; i < 256; i += TPB) {
        const float* src = (i < 128) ? W_sigma : W_mu;
        s_W[i] = ((const float4*)src)[i & 127];
    }
    __syncthreads();

    int t = blockIdx.x * TPB + threadIdx.x;
    if (t < BATCH * HEADS) g_acc[t] = 0.0f;
    if (t == 0) g_done = 0u;

    const int khalf = t & 1;
    const int pid   = t >> 1;                     // [0, 2*N_ATOM)
    const int which = (pid >= N_ATOM) ? 1 : 0;    // 0 = sigma, 1 = mu
    const int atom  = which ? (pid - N_ATOM) : pid;
    const float4* sW = s_W + which * 128;

    float4 x[4];
    float acc[HEADS];
    int wrow;
    float4* abase;   // atom's 8-float4 block

    if (atom < N_MOL) {
        const float4* f = (const float4*)(mol_feats + (size_t)atom * HID + khalf * 16);
        #pragma unroll
        for (int k = 0; k < 4; k++) x[k] = f[k];
        if (khalf == 0) {
            const float4* bsel = which ? (const float4*)b_mu : (const float4*)b_sigma;
            float4 b0 = bsel[0], b1 = bsel[1];
            acc[0] = b0.x; acc[1] = b0.y; acc[2] = b0.z; acc[3] = b0.w;
            acc[4] = b1.x; acc[5] = b1.y; acc[6] = b1.z; acc[7] = b1.w;
        } else {
            #pragma unroll
            for (int h = 0; h < HEADS; h++) acc[h] = 0.0f;
        }
        wrow = khalf * 16;
        abase = (float4*)(g_mol_half + (size_t)atom * 32);
    } else {
        int a = atom - N_MOL;
        const float4* f = (const float4*)(pro_feats + (size_t)a * HID + khalf * 16);
        const float4* s = (const float4*)(spatial   + (size_t)a * HID + khalf * 16);
        #pragma unroll
        for (int k = 0; k < 4; k++) {
            float4 fv = f[k], sv = s[k];
            x[k].x = fv.x * sv.x; x[k].y = fv.y * sv.y;
            x[k].z = fv.z * sv.z; x[k].w = fv.w * sv.w;
        }
        #pragma unroll
        for (int h = 0; h < HEADS; h++) acc[h] = 0.0f;
        wrow = HID + khalf * 16;
        abase = (float4*)(g_pro_half + (size_t)a * 32);
    }

    #pragma unroll
    for (int k = 0; k < 16; k++) {
        float xv = ((const float*)x)[k];
        float4 w0 = sW[(wrow + k) * 2 + 0];
        float4 w1 = sW[(wrow + k) * 2 + 1];
        acc[0] = fmaf(xv, w0.x, acc[0]); acc[1] = fmaf(xv, w0.y, acc[1]);
        acc[2] = fmaf(xv, w0.z, acc[2]); acc[3] = fmaf(xv, w0.w, acc[3]);
        acc[4] = fmaf(xv, w1.x, acc[4]); acc[5] = fmaf(xv, w1.y, acc[5]);
        acc[6] = fmaf(xv, w1.z, acc[6]); acc[7] = fmaf(xv, w1.w, acc[7]);
    }

    #pragma unroll
    for (int h = 0; h < HEADS; h++)
        acc[h] += __shfl_xor_sync(0xffffffffu, acc[h], 1);

    // khalf=0 lane owns elements 0-3, khalf=1 owns 4-7 (full combined sums).
    float v0 = acc[khalf * 4 + 0], v1 = acc[khalf * 4 + 1];
    float v2 = acc[khalf * 4 + 2], v3 = acc[khalf * 4 + 3];
    int rs = which * 2 + khalf;
    abase[rs]     = make_float4(v0, v1, v2, v3);
    abase[4 + rs] = make_float4(__expf(v0), __expf(v1), __expf(v2), __expf(v3));
}

// ---------------------------------------------------------------------------
// Kernel 2: per-pair sigma/mu via scalar branchless ELU (no MUFU, no predicates):
//   elu(m+p)+1.1 = fmax(m+p,0) + fmin(exp(m)*exp(p)+0.1, 1.1)
//   elu(m+p)+1.0 = fmax(m+p,0) + fmin(exp(m)*exp(p),     1.0)
// ---------------------------------------------------------------------------
__global__ void __launch_bounds__(TPB, 5) pair_kernel(
        float* __restrict__ mu_out, float* __restrict__ sigma_out,
        const float* __restrict__ W1, const float* __restrict__ b1,
        const float* __restrict__ W2, const float* __restrict__ b2,
        float* __restrict__ y_out) {
    __shared__ float4 s_sig [PSPLIT * 2];
    __shared__ float4 s_mu  [PSPLIT * 2];
    __shared__ float4 s_esig[PSPLIT * 2];
    __shared__ float4 s_emu [PSPLIT * 2];
    __shared__ float4 s_molsig[MPB * 2], s_molmu[MPB * 2];
    __shared__ float4 s_molesig[MPB * 2], s_molemu[MPB * 2];
    __shared__ float  s_red[(TPB / 32) * 8];
    __shared__ int    s_last;

    const int tile  = blockIdx.x;
    const int ph    = tile & 1;
    const int g     = tile >> 1;
    const int batch = g / GPB;
    const int mg    = g % GPB;
    const int mol0  = batch * MOL + mg * MPB;
    const int pro0  = ph * PSPLIT;

    // Stage pro tile: 250 atoms x 8 float4, de-interleaved.
    const float4* gp = (const float4*)g_pro_half + ((size_t)batch * PRO + pro0) * 8;
    for (int i = threadIdx.x; i < PSPLIT * 8; i += TPB) {
        int a = i >> 3, c = i & 7;
        float4 val = gp[i];
        int s = a * 2 + (c & 1);
        switch (c >> 1) {
            case 0: s_sig[s]  = val; break;
            case 1: s_mu[s]   = val; break;
            case 2: s_esig[s] = val; break;
            default: s_emu[s] = val; break;
        }
    }
    const float4* gm = (const float4*)g_mol_half + (size_t)mol0 * 8;
    if (threadIdx.x < MPB * 8) {
        int a = threadIdx.x >> 3, c = threadIdx.x & 7;
        float4 val = gm[threadIdx.x];
        int s = a * 2 + (c & 1);
        switch (c >> 1) {
            case 0: s_molsig[s]  = val; break;
            case 1: s_molmu[s]   = val; break;
            case 2: s_molesig[s] = val; break;
            default: s_molemu[s] = val; break;
        }
    }
    __syncthreads();

    float4 acc = make_float4(0.f, 0.f, 0.f, 0.f);
    const int h = threadIdx.x & 1;   // stride TPB is even -> parity fixed per thread

    #pragma unroll
    for (int lm = 0; lm < MPB; lm++) {
        const size_t base = ((size_t)(mol0 + lm) * PRO + pro0) * 2;
        float4* so = (float4*)sigma_out + base;
        float4* mo = (float4*)mu_out    + base;

        const float4 ms  = s_molsig[lm * 2 + h];
        const float4 ems = s_molesig[lm * 2 + h];
        const float4 mm  = s_molmu[lm * 2 + h];
        const float4 emm = s_molemu[lm * 2 + h];

        for (int v = threadIdx.x; v < PSPLIT * 2; v += TPB) {
            // ---- sigma: fmax(x,0) + fmin(e+0.1, 1.1) ----
            {
                const float4 ps  = s_sig[v];
                const float4 eps = s_esig[v];
                float4 sg;
                sg.x = fmaxf(ms.x + ps.x, 0.f) + fminf(fmaf(ems.x, eps.x, 0.1f), 1.1f);
                sg.y = fmaxf(ms.y + ps.y, 0.f) + fminf(fmaf(ems.y, eps.y, 0.1f), 1.1f);
                sg.z = fmaxf(ms.z + ps.z, 0.f) + fminf(fmaf(ems.z, eps.z, 0.1f), 1.1f);
                sg.w = fmaxf(ms.w + ps.w, 0.f) + fminf(fmaf(ems.w, eps.w, 0.1f), 1.1f);
                __stcs(so + v, sg);
            }
            // ---- mu: fmax(x,0) + fmin(e, 1) ----
            {
                const float4 pm  = s_mu[v];
                const float4 epm = s_emu[v];
                float4 mv;
                mv.x = fmaxf(mm.x + pm.x, 0.f) + fminf(emm.x * epm.x, 1.0f);
                mv.y = fmaxf(mm.y + pm.y, 0.f) + fminf(emm.y * epm.y, 1.0f);
                mv.z = fmaxf(mm.z + pm.z, 0.f) + fminf(emm.z * epm.z, 1.0f);
                mv.w = fmaxf(mm.w + pm.w, 0.f) + fminf(emm.w * epm.w, 1.0f);
                __stcs(mo + v, mv);
                acc.x += mv.x; acc.y += mv.y; acc.z += mv.z; acc.w += mv.w;
            }
        }
    }

    // Reduce: same-parity lanes share head set; xor offsets >=2 preserve parity.
    #pragma unroll
    for (int off = 16; off >= 2; off >>= 1) {
        acc.x += __shfl_xor_sync(0xffffffffu, acc.x, off);
        acc.y += __shfl_xor_sync(0xffffffffu, acc.y, off);
        acc.z += __shfl_xor_sync(0xffffffffu, acc.z, off);
        acc.w += __shfl_xor_sync(0xffffffffu, acc.w, off);
    }
    int warp = threadIdx.x >> 5, lane = threadIdx.x & 31;
    if (lane < 2) {   // lane0: heads 0-3, lane1: heads 4-7
        s_red[warp * 8 + lane * 4 + 0] = acc.x;
        s_red[warp * 8 + lane * 4 + 1] = acc.y;
        s_red[warp * 8 + lane * 4 + 2] = acc.z;
        s_red[warp * 8 + lane * 4 + 3] = acc.w;
    }
    __syncthreads();
    if (threadIdx.x < 8) {
        float s = 0.f;
        #pragma unroll
        for (int w = 0; w < TPB / 32; w++) s += s_red[w * 8 + threadIdx.x];
        atomicAdd(&g_acc[batch * HEADS + threadIdx.x], s);
        __threadfence();
    }
    __syncthreads();

    if (threadIdx.x == 0) {
        unsigned int done = atomicAdd(&g_done, 1u);
        s_last = (done == PAIR_BLOCKS - 1) ? 1 : 0;
    }
    __syncthreads();
    if (s_last && threadIdx.x < BATCH) {
        int b = threadIdx.x;
        float v[HEADS];
        #pragma unroll
        for (int hh = 0; hh < HEADS; hh++)
            v[hh] = __ldcg(&g_acc[b * HEADS + hh]) * 0.001f;
        float y = __ldg(&b2[0]);
        #pragma unroll
        for (int jj = 0; jj < 2 * HEADS; jj++) {
            float hsum = __ldg(&b1[jj]);
            #pragma unroll
            for (int hh = 0; hh < HEADS; hh++)
                hsum = fmaf(v[hh], __ldg(&W1[hh * 2 * HEADS + jj]), hsum);
            y = fmaf(elu1(hsum), __ldg(&W2[jj]), y);
        }
        y_out[b] = y;
    }
}

extern "C" void kernel_launch(void* const* d_in, const int* in_sizes, int n_in,
                              void* d_out, int out_size) {
    const float* mol_feats = (const float*)d_in[0];
    const float* pro_feats = (const float*)d_in[1];
    const float* spatial   = (const float*)d_in[2];
    const float* W_sigma   = (const float*)d_in[3];
    const float* b_sigma   = (const float*)d_in[4];
    const float* W_mu      = (const float*)d_in[5];
    const float* b_mu      = (const float*)d_in[6];
    const float* W1        = (const float*)d_in[7];
    const float* b1        = (const float*)d_in[8];
    const float* W2        = (const float*)d_in[9];
    const float* b2        = (const float*)d_in[10];

    float* out       = (float*)d_out;
    float* mu_out    = out;
    float* sigma_out = out + (size_t)PAIRS * HEADS;
    float* y_out     = out + (size_t)2 * PAIRS * HEADS;

    int total_threads = 4 * N_ATOM;   // 140800 = 550 blocks exactly
    precompute_kernel<<<total_threads / TPB, TPB>>>(
        mol_feats, pro_feats, spatial, W_sigma, b_sigma, W_mu, b_mu);
    pair_kernel<<<PAIR_BLOCKS, TPB>>>(mu_out, sigma_out, W1, b1, W2, b2, y_out);
}